// round 6
// baseline (speedup 1.0000x reference)
#include <cuda_runtime.h>
#include <math.h>

// Problem constants
#define Bsz 8
#define Lseq 4096
#define Hdim 512
#define N2 32
#define HN (Hdim * N2)
#define NC 32                // number of sequence chunks
#define CHUNK (Lseq / NC)    // 128 steps per chunk
#define NWARPS (NC * Bsz * 128)  // warps per pass: 32768 (4 scans per warp)

typedef unsigned long long u64;

// ---------------------------------------------------------------------------
// Packed f32x2 helpers (Blackwell sm_103a)
// ---------------------------------------------------------------------------
__device__ __forceinline__ u64 pk2(float lo, float hi) {
    u64 r;
    asm("mov.b64 %0, {%1, %2};" : "=l"(r) : "f"(lo), "f"(hi));
    return r;
}
__device__ __forceinline__ float2 upk2(u64 v) {
    float2 f;
    asm("mov.b64 {%0, %1}, %2;" : "=f"(f.x), "=f"(f.y) : "l"(v));
    return f;
}
__device__ __forceinline__ u64 fma2(u64 a, u64 b, u64 c) {
    u64 d;
    asm("fma.rn.f32x2 %0, %1, %2, %3;" : "=l"(d) : "l"(a), "l"(b), "l"(c));
    return d;
}
__device__ __forceinline__ u64 mul2(u64 a, u64 b) {
    u64 d;
    asm("mul.rn.f32x2 %0, %1, %2;" : "=l"(d) : "l"(a), "l"(b));
    return d;
}

// ---------------------------------------------------------------------------
// Precomputed parameters and inter-chunk scratch
// ---------------------------------------------------------------------------
__device__ float g_dAre[HN];
__device__ float g_dAim[HN];
__device__ float g_dBre[HN];
__device__ float g_dBim[HN];
__device__ float g_C2re[HN];     //  2 * C_re
__device__ float g_C2imN[HN];    // -2 * C_im
__device__ float g_dAPre[HN];    // dA^CHUNK
__device__ float g_dAPim[HN];

__device__ float g_locre[NC * Bsz * HN];  // chunk-local final states
__device__ float g_locim[NC * Bsz * HN];
__device__ float g_carre[NC * Bsz * HN];  // chunk carry-in states
__device__ float g_carim[NC * Bsz * HN];

// ZOH discretization: dA = exp(dt*A), dB = B * expm1(dt*A)/A, plus dA^CHUNK
__global__ void s4d_precompute(const float* __restrict__ log_dt,
                               const float* __restrict__ arl,
                               const float* __restrict__ aim,
                               const float* __restrict__ Bre,
                               const float* __restrict__ Bim,
                               const float* __restrict__ Cre,
                               const float* __restrict__ Cim) {
    int i = blockIdx.x * blockDim.x + threadIdx.x;
    if (i >= HN) return;
    int h = i / N2;
    float dt   = expf(log_dt[h]);
    float are  = -expf(arl[i]);
    float aimv = aim[i];
    float zre = are * dt;
    float zim = aimv * dt;
    float sz, cz;
    sincosf(zim, &sz, &cz);
    float ez = expf(zre);
    g_dAre[i] = ez * cz;
    g_dAim[i] = ez * sz;
    // expm1(z) = expm1(zre)*cos(zim) - 2 sin^2(zim/2)  + i * e^{zre} sin(zim)
    float sh = sinf(0.5f * zim);
    float em1re = expm1f(zre) * cz - 2.0f * sh * sh;
    float em1im = ez * sz;
    float inv = 1.0f / (are * are + aimv * aimv);
    float fre = (em1re * are + em1im * aimv) * inv;
    float fim = (em1im * are - em1re * aimv) * inv;
    float bre = Bre[i], bim = Bim[i];
    g_dBre[i] = bre * fre - bim * fim;
    g_dBim[i] = bre * fim + bim * fre;
    g_C2re[i]  =  2.0f * Cre[i];
    g_C2imN[i] = -2.0f * Cim[i];
    // dA^CHUNK in double precision: exp(CHUNK * z)
    double zre_d = (double)are * (double)dt * (double)CHUNK;
    double zim_d = (double)aimv * (double)dt * (double)CHUNK;
    double ezd = exp(zre_d);
    g_dAPre[i] = (float)(ezd * cos(zim_d));
    g_dAPim[i] = (float)(ezd * sin(zim_d));
}

// ---------------------------------------------------------------------------
// Pass 1: chunk-local state-only scan (zero init). 8 lanes per scan,
// 4 modes per lane, 4 scans per warp.
// ---------------------------------------------------------------------------
__global__ void __launch_bounds__(256, 4)
s4d_pass1(const float* __restrict__ x) {
    const int lane = threadIdx.x & 31;
    const int gw   = blockIdx.x * 8 + (threadIdx.x >> 5);  // [0, NWARPS)
    const int sub  = lane >> 3;
    const int j    = lane & 7;

    const int hb = gw & 127;
    const int b  = (gw >> 7) & 7;
    const int c  = gw >> 10;        // chunk index [0, NC)
    const int h  = hb * 4 + sub;

    const int pb = h * N2 + 4 * j;
    float4 ar = *reinterpret_cast<const float4*>(&g_dAre[pb]);
    float4 ai = *reinterpret_cast<const float4*>(&g_dAim[pb]);
    float4 br = *reinterpret_cast<const float4*>(&g_dBre[pb]);
    float4 bi = *reinterpret_cast<const float4*>(&g_dBim[pb]);

    const u64 dAre0 = pk2(ar.x, ar.y), dAre1 = pk2(ar.z, ar.w);
    const u64 dAim0 = pk2(ai.x, ai.y), dAim1 = pk2(ai.z, ai.w);
    const u64 dAimN0 = pk2(-ai.x, -ai.y), dAimN1 = pk2(-ai.z, -ai.w);
    const u64 dBre0 = pk2(br.x, br.y), dBre1 = pk2(br.z, br.w);
    const u64 dBim0 = pk2(bi.x, bi.y), dBim1 = pk2(bi.z, bi.w);

    u64 sre0 = 0ull, sim0 = 0ull, sre1 = 0ull, sim1 = 0ull;

    const float* __restrict__ xq =
        x + ((size_t)b * Lseq + (size_t)c * CHUNK) * Hdim + h;

#define P1_STEP(XV) do {                                                  \
        u64 x2 = pk2((XV), (XV));                                         \
        u64 nre0 = fma2(dAre0, sre0, fma2(dAimN0, sim0, mul2(dBre0, x2)));\
        u64 nim0 = fma2(dAim0, sre0, fma2(dAre0, sim0, mul2(dBim0, x2)));\
        u64 nre1 = fma2(dAre1, sre1, fma2(dAimN1, sim1, mul2(dBre1, x2)));\
        u64 nim1 = fma2(dAim1, sre1, fma2(dAre1, sim1, mul2(dBim1, x2)));\
        sre0 = nre0; sim0 = nim0; sre1 = nre1; sim1 = nim1;               \
    } while (0)

    // group-of-4 software pipeline, immediate LDG offsets
    float x0 = __ldg(xq);
    float x1 = __ldg(xq + Hdim);
    float x2v = __ldg(xq + 2 * Hdim);
    float x3 = __ldg(xq + 3 * Hdim);
    #pragma unroll 1
    for (int g = 0; g < CHUNK / 4 - 1; ++g) {
        float n0 = __ldg(xq + 4 * Hdim);
        float n1 = __ldg(xq + 5 * Hdim);
        float n2 = __ldg(xq + 6 * Hdim);
        float n3 = __ldg(xq + 7 * Hdim);
        P1_STEP(x0); P1_STEP(x1); P1_STEP(x2v); P1_STEP(x3);
        x0 = n0; x1 = n1; x2v = n2; x3 = n3;
        xq += 4 * Hdim;
    }
    P1_STEP(x0); P1_STEP(x1); P1_STEP(x2v); P1_STEP(x3);
#undef P1_STEP

    const size_t idx = ((size_t)(c * Bsz + b) * Hdim + h) * N2 + 4 * j;
    float2 r0 = upk2(sre0), i0 = upk2(sim0);
    float2 r1 = upk2(sre1), i1 = upk2(sim1);
    *reinterpret_cast<float4*>(&g_locre[idx]) = make_float4(r0.x, r0.y, r1.x, r1.y);
    *reinterpret_cast<float4*>(&g_locim[idx]) = make_float4(i0.x, i0.y, i1.x, i1.y);
}

// ---------------------------------------------------------------------------
// Carry combine: per (b,h,n), exclusive scan over chunks.
// ---------------------------------------------------------------------------
__global__ void s4d_carry() {
    int i = blockIdx.x * blockDim.x + threadIdx.x;  // [0, Bsz*HN)
    if (i >= Bsz * HN) return;
    int b = i / HN;
    int r = i % HN;  // h*N2 + n
    float a_re = g_dAPre[r], a_im = g_dAPim[r];
    float cre = 0.0f, cim = 0.0f;
    #pragma unroll
    for (int c = 0; c < NC; ++c) {
        size_t idx = (size_t)(c * Bsz + b) * HN + r;
        g_carre[idx] = cre;
        g_carim[idx] = cim;
        float lre = g_locre[idx], lim = g_locim[idx];
        float nre = fmaf(a_re, cre, fmaf(-a_im, cim, lre));
        float nim = fmaf(a_im, cre, fmaf(a_re, cim, lim));
        cre = nre; cim = nim;
    }
}

// ---------------------------------------------------------------------------
// Pass 2: full scan per chunk with carry-in init. Writes ys (+ final state
// from the last chunk). stateMode: 0 none, 1 real-only, 2 planar re/im
// ---------------------------------------------------------------------------
__global__ void __launch_bounds__(256, 4)
s4d_pass2(const float* __restrict__ x,
          const float* __restrict__ Dv,
          float* __restrict__ out,
          int stateMode) {
    const int lane = threadIdx.x & 31;
    const int gw   = blockIdx.x * 8 + (threadIdx.x >> 5);
    const int sub  = lane >> 3;
    const int j    = lane & 7;

    const int hb = gw & 127;
    const int b  = (gw >> 7) & 7;
    const int c  = gw >> 10;
    const int h  = hb * 4 + sub;

    const int pb = h * N2 + 4 * j;
    float4 ar = *reinterpret_cast<const float4*>(&g_dAre[pb]);
    float4 ai = *reinterpret_cast<const float4*>(&g_dAim[pb]);
    float4 br = *reinterpret_cast<const float4*>(&g_dBre[pb]);
    float4 bi = *reinterpret_cast<const float4*>(&g_dBim[pb]);
    float4 cr = *reinterpret_cast<const float4*>(&g_C2re[pb]);
    float4 ci = *reinterpret_cast<const float4*>(&g_C2imN[pb]);

    const u64 dAre0 = pk2(ar.x, ar.y), dAre1 = pk2(ar.z, ar.w);
    const u64 dAim0 = pk2(ai.x, ai.y), dAim1 = pk2(ai.z, ai.w);
    const u64 dAimN0 = pk2(-ai.x, -ai.y), dAimN1 = pk2(-ai.z, -ai.w);
    const u64 dBre0 = pk2(br.x, br.y), dBre1 = pk2(br.z, br.w);
    const u64 dBim0 = pk2(bi.x, bi.y), dBim1 = pk2(bi.z, bi.w);
    const u64 C2re0 = pk2(cr.x, cr.y), C2re1 = pk2(cr.z, cr.w);
    const u64 C2imN0 = pk2(ci.x, ci.y), C2imN1 = pk2(ci.z, ci.w);

    const float Dh = Dv[h];

    // init state from carry
    const size_t cidx = ((size_t)(c * Bsz + b) * Hdim + h) * N2 + 4 * j;
    float4 crre = *reinterpret_cast<const float4*>(&g_carre[cidx]);
    float4 crim = *reinterpret_cast<const float4*>(&g_carim[cidx]);
    u64 sre0 = pk2(crre.x, crre.y), sre1 = pk2(crre.z, crre.w);
    u64 sim0 = pk2(crim.x, crim.y), sim1 = pk2(crim.z, crim.w);

    const size_t base = ((size_t)b * Lseq + (size_t)c * CHUNK) * Hdim + h;
    const float* __restrict__ xq = x + base + Hdim;  // prefetch pointer
    float* __restrict__ yp = out + base;

    float xv = __ldg(x + base);

#define P2_STEP(XV) do {                                                  \
        u64 x2 = pk2((XV), (XV));                                         \
        u64 nre0 = fma2(dAre0, sre0, fma2(dAimN0, sim0, mul2(dBre0, x2)));\
        u64 nim0 = fma2(dAim0, sre0, fma2(dAre0, sim0, mul2(dBim0, x2)));\
        u64 nre1 = fma2(dAre1, sre1, fma2(dAimN1, sim1, mul2(dBre1, x2)));\
        u64 nim1 = fma2(dAim1, sre1, fma2(dAre1, sim1, mul2(dBim1, x2)));\
        u64 acc = mul2(C2re0, nre0);                                      \
        acc = fma2(C2imN0, nim0, acc);                                    \
        acc = fma2(C2re1, nre1, acc);                                     \
        acc = fma2(C2imN1, nim1, acc);                                    \
        sre0 = nre0; sim0 = nim0; sre1 = nre1; sim1 = nim1;               \
        float2 a = upk2(acc);                                             \
        float cc = a.x + a.y;                                             \
        cc += __shfl_xor_sync(0xffffffffu, cc, 1);                        \
        cc += __shfl_xor_sync(0xffffffffu, cc, 2);                        \
        cc += __shfl_xor_sync(0xffffffffu, cc, 4);                        \
        float yv = fmaf(Dh, (XV), cc);                                    \
        float gl = 0.5f * yv * (1.0f + erff(yv * 0.70710678118654752f));  \
        if (j == 0) *yp = gl;                                             \
        yp += Hdim;                                                       \
    } while (0)

    #pragma unroll 4
    for (int t = 0; t < CHUNK - 1; ++t) {
        float xn = __ldg(xq);
        xq += Hdim;
        P2_STEP(xv);
        xv = xn;
    }
    P2_STEP(xv);  // peeled last step: no prefetch load
#undef P2_STEP

    if (stateMode > 0 && c == NC - 1) {
        float2 r0 = upk2(sre0), i0 = upk2(sim0);
        float2 r1 = upk2(sre1), i1 = upk2(sim1);
        const size_t ysEnd = (size_t)Bsz * Lseq * Hdim;
        const size_t stN   = (size_t)Bsz * Hdim * N2;
        const size_t idx   = ((size_t)b * Hdim + h) * N2 + 4 * j;
        *reinterpret_cast<float4*>(out + ysEnd + idx) =
            make_float4(r0.x, r0.y, r1.x, r1.y);
        if (stateMode > 1) {
            *reinterpret_cast<float4*>(out + ysEnd + stN + idx) =
                make_float4(i0.x, i0.y, i1.x, i1.y);
        }
    }
}

// ---------------------------------------------------------------------------
// Launch
// ---------------------------------------------------------------------------
extern "C" void kernel_launch(void* const* d_in, const int* in_sizes, int n_in,
                              void* d_out, int out_size) {
    const float* x      = (const float*)d_in[0];
    const float* log_dt = (const float*)d_in[1];
    const float* arl    = (const float*)d_in[2];
    const float* aim    = (const float*)d_in[3];
    const float* Bre    = (const float*)d_in[4];
    const float* Bim    = (const float*)d_in[5];
    const float* Cre    = (const float*)d_in[6];
    const float* Cim    = (const float*)d_in[7];
    const float* Dv     = (const float*)d_in[8];
    float* out = (float*)d_out;

    s4d_precompute<<<(HN + 255) / 256, 256>>>(log_dt, arl, aim, Bre, Bim, Cre, Cim);

    const long long ysElems = (long long)Bsz * Lseq * Hdim;   // 16,777,216
    const long long stN     = (long long)Bsz * Hdim * N2;     // 131,072
    int stateMode = 0;
    if ((long long)out_size >= ysElems + 2 * stN) stateMode = 2;
    else if ((long long)out_size >= ysElems + stN) stateMode = 1;

    // NWARPS=32768 warps per pass, 8 warps per 256-thread block => 4096 blocks
    s4d_pass1<<<NWARPS / 8, 256>>>(x);
    s4d_carry<<<(Bsz * HN + 255) / 256, 256>>>();
    s4d_pass2<<<NWARPS / 8, 256>>>(x, Dv, out, stateMode);
}

// round 7
// speedup vs baseline: 1.0569x; 1.0569x over previous
#include <cuda_runtime.h>
#include <math.h>

// Problem constants
#define Hd 512
#define L 4096
#define B 8
#define N2 32
#define HN (Hd * N2)
#define T 64            // chunk length
#define NCH (L / T)     // 64 chunks per sequence
#define CB (NCH * B)    // 512 chunk-rows
#define Q 64            // 2*N2 (re block + im block)

// ---------------------------------------------------------------------------
// Device-global parameter / scratch arrays
// ---------------------------------------------------------------------------
__device__ float g_dAre[HN], g_dAim[HN];
__device__ float g_dBre[HN], g_dBim[HN];
__device__ float g_C2re[HN], g_C2imN[HN];
__device__ float g_dATre[HN], g_dATim[HN];     // dA^T (double-derived)
__device__ float g_E[Hd * T * Q];              // [h][l][q]: (dA^l dB) re|im
__device__ float g_W[Hd * Q * T];              // [h][q][t]: 2Re/-2Im(C dA^{t+1})
__device__ float g_K[Hd * T];                  // conv kernel 2Re(C dA^l dB)
__device__ float g_loc[(size_t)Hd * CB * Q];   // chunk-local states
__device__ float g_S0[(size_t)Hd * CB * Q];    // chunk carry-in states
__device__ float g_corr[(size_t)Hd * CB * T];  // per-(h,chunk,t) correction

// ---------------------------------------------------------------------------
// K0: per-(h,n) discretization + E/W tables
// ---------------------------------------------------------------------------
__global__ void k_prep(const float* __restrict__ log_dt,
                       const float* __restrict__ arl,
                       const float* __restrict__ aim,
                       const float* __restrict__ Bre,
                       const float* __restrict__ Bim,
                       const float* __restrict__ Cre,
                       const float* __restrict__ Cim) {
    int i = blockIdx.x * blockDim.x + threadIdx.x;
    if (i >= HN) return;
    int h = i >> 5, n = i & 31;
    float dt   = expf(log_dt[h]);
    float are  = -expf(arl[i]);
    float aimv = aim[i];
    float zre = are * dt, zim = aimv * dt;
    float sz, cz; sincosf(zim, &sz, &cz);
    float ez = expf(zre);
    float dre = ez * cz, dimv = ez * sz;   // dA
    g_dAre[i] = dre; g_dAim[i] = dimv;
    // dB = B * expm1(dtA)/A  (cancellation-stable expm1)
    float sh = sinf(0.5f * zim);
    float em1re = expm1f(zre) * cz - 2.0f * sh * sh;
    float em1im = ez * sz;
    float inv = 1.0f / (are * are + aimv * aimv);
    float fre = (em1re * are + em1im * aimv) * inv;
    float fim = (em1im * are - em1re * aimv) * inv;
    float bre0 = Bre[i], bim0 = Bim[i];
    float dbre = bre0 * fre - bim0 * fim;
    float dbim = bre0 * fim + bim0 * fre;
    g_dBre[i] = dbre; g_dBim[i] = dbim;
    g_C2re[i]  =  2.0f * Cre[i];
    g_C2imN[i] = -2.0f * Cim[i];
    // dA^T via double (exact chunk-step matrix)
    double zred = (double)are * (double)dt * (double)T;
    double zimd = (double)aimv * (double)dt * (double)T;
    double ezd = exp(zred);
    g_dATre[i] = (float)(ezd * cos(zimd));
    g_dATim[i] = (float)(ezd * sin(zimd));
    // E[l] = dA^l dB ; W[t] = C dA^{t+1}
    float pre = dbre, pim = dbim;
    float cre0 = Cre[i], cim0 = Cim[i];
    float wre = cre0 * dre - cim0 * dimv;
    float wim = cre0 * dimv + cim0 * dre;
    for (int l = 0; l < T; ++l) {
        g_E[(h * T + l) * Q + n]      = pre;
        g_E[(h * T + l) * Q + 32 + n] = pim;
        g_W[((h * Q) + n) * T + l]      =  2.0f * wre;
        g_W[((h * Q) + 32 + n) * T + l] = -2.0f * wim;
        float tre = pre * dre - pim * dimv; pim = pre * dimv + pim * dre; pre = tre;
        float ure = wre * dre - wim * dimv; wim = wre * dimv + wim * dre; wre = ure;
    }
}

// K0b: conv kernel K[h][l] = sum_n (2Cre*Ere - 2Cim*Eim)
__global__ void k_K() {
    int i = blockIdx.x * blockDim.x + threadIdx.x;  // h*T + l
    if (i >= Hd * T) return;
    int h = i >> 6;
    const float* e   = &g_E[(size_t)i * Q];
    const float* c2r = &g_C2re[h * 32];
    const float* c2i = &g_C2imN[h * 32];
    float s = 0.0f;
    #pragma unroll 8
    for (int n = 0; n < 32; ++n)
        s = fmaf(c2r[n], e[n], fmaf(c2i[n], e[32 + n], s));
    g_K[i] = s;
}

// ---------------------------------------------------------------------------
// K1: chunk-local states, GEMM-style: loc[h][cb][q] = sum_l E[h][l][q]*xrev[cb][l]
// grid (Hd, CB/256), block 256
// ---------------------------------------------------------------------------
__global__ void __launch_bounds__(256) k_loc(const float* __restrict__ x) {
    __shared__ float Es[T * Q];       // 16KB
    __shared__ float xrs[32 * 65];    // padded
    const int h = blockIdx.x;
    const int tid = threadIdx.x;
    for (int k = tid; k < T * Q; k += 256) Es[k] = g_E[(size_t)h * T * Q + k];
    const int cc = tid & 31, w = tid >> 5, q0 = w * 8;
    for (int ct = 0; ct < 8; ++ct) {
        const int cb0 = blockIdx.y * 256 + ct * 32;
        __syncthreads();
        for (int k = tid; k < 32 * T; k += 256) {
            int c2 = k >> 6, l = k & 63;
            int cb = cb0 + c2, b = cb & 7, c = cb >> 3;
            xrs[c2 * 65 + l] = x[((size_t)b * L + c * T + (T - 1 - l)) * Hd + h];
        }
        __syncthreads();
        float acc[8] = {0,0,0,0,0,0,0,0};
        #pragma unroll 8
        for (int l = 0; l < T; ++l) {
            float xv = xrs[cc * 65 + l];
            float4 e0 = *reinterpret_cast<const float4*>(&Es[l * Q + q0]);
            float4 e1 = *reinterpret_cast<const float4*>(&Es[l * Q + q0 + 4]);
            acc[0] = fmaf(e0.x, xv, acc[0]); acc[1] = fmaf(e0.y, xv, acc[1]);
            acc[2] = fmaf(e0.z, xv, acc[2]); acc[3] = fmaf(e0.w, xv, acc[3]);
            acc[4] = fmaf(e1.x, xv, acc[4]); acc[5] = fmaf(e1.y, xv, acc[5]);
            acc[6] = fmaf(e1.z, xv, acc[6]); acc[7] = fmaf(e1.w, xv, acc[7]);
        }
        size_t o = ((size_t)h * CB + (cb0 + cc)) * Q + q0;
        *reinterpret_cast<float4*>(&g_loc[o])     = make_float4(acc[0], acc[1], acc[2], acc[3]);
        *reinterpret_cast<float4*>(&g_loc[o + 4]) = make_float4(acc[4], acc[5], acc[6], acc[7]);
    }
}

// ---------------------------------------------------------------------------
// K2: carry scan over chunks (exclusive) + final state output
// ---------------------------------------------------------------------------
__global__ void k_carry(float* __restrict__ out, int stateMode) {
    int i = blockIdx.x * blockDim.x + threadIdx.x;
    if (i >= HN * B) return;
    int n = i & 31, h = (i >> 5) & (Hd - 1), b = i >> 14;
    int p = h * 32 + n;
    float aRe = g_dATre[p], aIm = g_dATim[p];
    float cre = 0.0f, cim = 0.0f;
    for (int c = 0; c < NCH; ++c) {
        size_t o = ((size_t)h * CB + c * B + b) * Q + n;
        g_S0[o] = cre; g_S0[o + 32] = cim;
        float lre = g_loc[o], lim = g_loc[o + 32];
        float nre = fmaf(aRe, cre, fmaf(-aIm, cim, lre));
        float nim = fmaf(aIm, cre, fmaf(aRe, cim, lim));
        cre = nre; cim = nim;
    }
    if (stateMode > 0) {
        size_t ysEnd = (size_t)B * L * Hd;
        size_t idx = ((size_t)b * Hd + h) * N2 + n;
        out[ysEnd + idx] = cre;
        if (stateMode > 1) out[ysEnd + (size_t)B * Hd * N2 + idx] = cim;
    }
}

// ---------------------------------------------------------------------------
// K3: correction GEMM: corr[h][cb][t] = sum_q W[h][q][t] * S0[h][cb][q]
// grid (Hd, CB/256), block 256
// ---------------------------------------------------------------------------
__global__ void __launch_bounds__(256) k_corr() {
    __shared__ float Ws[Q * T];       // 16KB
    __shared__ float s0s[32 * 65];
    const int h = blockIdx.x;
    const int tid = threadIdx.x;
    for (int k = tid; k < Q * T; k += 256) Ws[k] = g_W[(size_t)h * Q * T + k];
    const int cc = tid & 31, w = tid >> 5, t0 = w * 8;
    for (int ct = 0; ct < 8; ++ct) {
        const int cb0 = blockIdx.y * 256 + ct * 32;
        __syncthreads();
        for (int k = tid; k < 32 * Q; k += 256) {
            int c2 = k >> 6, q = k & 63;
            s0s[c2 * 65 + q] = g_S0[((size_t)h * CB + cb0 + c2) * Q + q];
        }
        __syncthreads();
        float acc[8] = {0,0,0,0,0,0,0,0};
        #pragma unroll 8
        for (int q = 0; q < Q; ++q) {
            float sv = s0s[cc * 65 + q];
            float4 w0 = *reinterpret_cast<const float4*>(&Ws[q * T + t0]);
            float4 w1 = *reinterpret_cast<const float4*>(&Ws[q * T + t0 + 4]);
            acc[0] = fmaf(w0.x, sv, acc[0]); acc[1] = fmaf(w0.y, sv, acc[1]);
            acc[2] = fmaf(w0.z, sv, acc[2]); acc[3] = fmaf(w0.w, sv, acc[3]);
            acc[4] = fmaf(w1.x, sv, acc[4]); acc[5] = fmaf(w1.y, sv, acc[5]);
            acc[6] = fmaf(w1.z, sv, acc[6]); acc[7] = fmaf(w1.w, sv, acc[7]);
        }
        size_t o = ((size_t)h * CB + cb0 + cc) * T + t0;
        *reinterpret_cast<float4*>(&g_corr[o])     = make_float4(acc[0], acc[1], acc[2], acc[3]);
        *reinterpret_cast<float4*>(&g_corr[o + 4]) = make_float4(acc[4], acc[5], acc[6], acc[7]);
    }
}

// ---------------------------------------------------------------------------
// K4: output = causal conv(K,x) + corr + D*x, then exact GELU. Coalesced I/O.
// grid (CB, Hd/32), block 256: 32 h-lanes x 8 t-octet warps
// ---------------------------------------------------------------------------
__global__ void __launch_bounds__(256) k_out(const float* __restrict__ x,
                                             const float* __restrict__ Dv,
                                             float* __restrict__ out) {
    __shared__ float xs[32 * 133];   // [hh][row], rows: 63 zero-pad + 64 real
    __shared__ float Ks[32 * 65];    // [hh][l]
    const int cb = blockIdx.x, h0 = blockIdx.y * 32;
    const int b = cb & 7, c = cb >> 3;
    const int tid = threadIdx.x;
    for (int k = tid; k < 32 * 63; k += 256) {
        int hh = k & 31, r = k >> 5;
        xs[hh * 133 + r] = 0.0f;
    }
    for (int k = tid; k < 32 * 64; k += 256) {
        int hh = k & 31, tt = k >> 5;
        xs[hh * 133 + 63 + tt] = x[((size_t)b * L + c * T + tt) * Hd + h0 + hh];
    }
    for (int k = tid; k < 32 * 64; k += 256) {
        int hh = k & 31, l = k >> 5;
        Ks[hh * 65 + l] = g_K[(h0 + hh) * T + l];
    }
    __syncthreads();

    const int hh = tid & 31, w = tid >> 5, t0 = w * 8;
    size_t co = ((size_t)(h0 + hh) * CB + cb) * T + t0;
    float4 c0 = *reinterpret_cast<const float4*>(&g_corr[co]);
    float4 c1 = *reinterpret_cast<const float4*>(&g_corr[co + 4]);
    float acc[8] = {c0.x, c0.y, c0.z, c0.w, c1.x, c1.y, c1.z, c1.w};

    const float* xrow = &xs[hh * 133];
    const float* krow = &Ks[hh * 65];
    for (int lt = 0; lt <= w; ++lt) {     // triangular skip (warp-uniform)
        const int l0 = lt * 8;
        const int rb = 63 + t0 - l0 - 7;
        float xw[15];
        #pragma unroll
        for (int j = 0; j < 15; ++j) xw[j] = xrow[rb + j];
        float kk[8];
        #pragma unroll
        for (int i = 0; i < 8; ++i) kk[i] = krow[l0 + i];
        #pragma unroll
        for (int i = 0; i < 8; ++i)
            #pragma unroll
            for (int j = 0; j < 8; ++j)
                acc[j] = fmaf(kk[i], xw[7 + j - i], acc[j]);
    }

    const float Dh = Dv[h0 + hh];
    #pragma unroll
    for (int j = 0; j < 8; ++j) {
        float xv = xrow[63 + t0 + j];
        float yv = fmaf(Dh, xv, acc[j]);
        float g = 0.5f * yv * (1.0f + erff(yv * 0.70710678118654752f));
        out[((size_t)b * L + c * T + t0 + j) * Hd + h0 + hh] = g;
    }
}

// ---------------------------------------------------------------------------
// Launch
// ---------------------------------------------------------------------------
extern "C" void kernel_launch(void* const* d_in, const int* in_sizes, int n_in,
                              void* d_out, int out_size) {
    const float* x      = (const float*)d_in[0];
    const float* log_dt = (const float*)d_in[1];
    const float* arl    = (const float*)d_in[2];
    const float* aim    = (const float*)d_in[3];
    const float* Bre    = (const float*)d_in[4];
    const float* Bim    = (const float*)d_in[5];
    const float* Cre    = (const float*)d_in[6];
    const float* Cim    = (const float*)d_in[7];
    const float* Dv     = (const float*)d_in[8];
    float* out = (float*)d_out;

    const long long ysElems = (long long)B * L * Hd;   // 16,777,216
    const long long stN     = (long long)B * Hd * N2;  // 131,072
    int stateMode = 0;
    if ((long long)out_size >= ysElems + 2 * stN) stateMode = 2;
    else if ((long long)out_size >= ysElems + stN) stateMode = 1;

    k_prep<<<(HN + 255) / 256, 256>>>(log_dt, arl, aim, Bre, Bim, Cre, Cim);
    k_K<<<(Hd * T + 255) / 256, 256>>>();
    k_loc<<<dim3(Hd, CB / 256), 256>>>(x);
    k_carry<<<(HN * B + 255) / 256, 256>>>(out, stateMode);
    k_corr<<<dim3(Hd, CB / 256), 256>>>();
    k_out<<<dim3(CB, Hd / 32), 256>>>(x, Dv, out);
}

// round 8
// speedup vs baseline: 1.1061x; 1.0465x over previous
#include <cuda_runtime.h>
#include <math.h>

// Problem constants
#define Hd 512
#define L 4096
#define B 8
#define N2 32
#define HN (Hd * N2)
#define T 64            // chunk length
#define NCH (L / T)     // 64 chunks per sequence
#define CB (NCH * B)    // 512 chunk-rows
#define Q 64            // 2*N2 (re block + im block)
#define BL (B * L)      // 32768

typedef unsigned long long u64;

__device__ __forceinline__ u64 pk2(float lo, float hi) {
    u64 r; asm("mov.b64 %0, {%1, %2};" : "=l"(r) : "f"(lo), "f"(hi)); return r;
}
__device__ __forceinline__ float2 upk2(u64 v) {
    float2 f; asm("mov.b64 {%0, %1}, %2;" : "=f"(f.x), "=f"(f.y) : "l"(v)); return f;
}
__device__ __forceinline__ u64 fma2(u64 a, u64 b, u64 c) {
    u64 d; asm("fma.rn.f32x2 %0, %1, %2, %3;" : "=l"(d) : "l"(a), "l"(b), "l"(c)); return d;
}

// ---------------------------------------------------------------------------
// Device-global parameter / scratch arrays
// ---------------------------------------------------------------------------
__device__ float g_C2re[HN], g_C2imN[HN];
__device__ float g_dATre[HN], g_dATim[HN];         // dA^T (double-derived)
__device__ __align__(16) float g_E[Hd * T * Q];    // [h][tau][q]: dA^{T-1-tau} dB (re|im)
__device__ __align__(16) float g_W[Hd * Q * T];    // [h][q][t]: 2Re/-2Im(C dA^{t+1})
__device__ float g_K[Hd * T];                      // conv kernel 2Re(C dA^l dB)
__device__ float g_xT[(size_t)Hd * BL];            // transposed x: [h][b*L+t]
__device__ float g_loc[(size_t)Hd * Q * CB];       // [h][q][cb] chunk-local states
__device__ float g_S0[(size_t)Hd * Q * CB];        // [h][q][cb] carry-in states
__device__ __align__(16) float g_corr[(size_t)Hd * CB * T];  // [h][cb][t]

// ---------------------------------------------------------------------------
// K0: per-(h,n) discretization + E/W tables
// ---------------------------------------------------------------------------
__global__ void k_prep(const float* __restrict__ log_dt,
                       const float* __restrict__ arl,
                       const float* __restrict__ aim,
                       const float* __restrict__ Bre,
                       const float* __restrict__ Bim,
                       const float* __restrict__ Cre,
                       const float* __restrict__ Cim) {
    int i = blockIdx.x * blockDim.x + threadIdx.x;
    if (i >= HN) return;
    int h = i >> 5, n = i & 31;
    float dt   = expf(log_dt[h]);
    float are  = -expf(arl[i]);
    float aimv = aim[i];
    float zre = are * dt, zim = aimv * dt;
    float sz, cz; sincosf(zim, &sz, &cz);
    float ez = expf(zre);
    float dre = ez * cz, dimv = ez * sz;   // dA
    // dB = B * expm1(dtA)/A  (cancellation-stable expm1)
    float sh = sinf(0.5f * zim);
    float em1re = expm1f(zre) * cz - 2.0f * sh * sh;
    float em1im = ez * sz;
    float inv = 1.0f / (are * are + aimv * aimv);
    float fre = (em1re * are + em1im * aimv) * inv;
    float fim = (em1im * are - em1re * aimv) * inv;
    float bre0 = Bre[i], bim0 = Bim[i];
    float dbre = bre0 * fre - bim0 * fim;
    float dbim = bre0 * fim + bim0 * fre;
    g_C2re[i]  =  2.0f * Cre[i];
    g_C2imN[i] = -2.0f * Cim[i];
    // dA^T via double (exact chunk-step matrix)
    double zred = (double)are * (double)dt * (double)T;
    double zimd = (double)aimv * (double)dt * (double)T;
    double ezd = exp(zred);
    g_dATre[i] = (float)(ezd * cos(zimd));
    g_dATim[i] = (float)(ezd * sin(zimd));
    // E[tau] = dA^{T-1-tau} dB (reversed rows) ; W[t] = C dA^{t+1}
    float pre = dbre, pim = dbim;
    float cre0 = Cre[i], cim0 = Cim[i];
    float wre = cre0 * dre - cim0 * dimv;
    float wim = cre0 * dimv + cim0 * dre;
    for (int l = 0; l < T; ++l) {
        g_E[((size_t)h * T + (T - 1 - l)) * Q + n]      = pre;
        g_E[((size_t)h * T + (T - 1 - l)) * Q + 32 + n] = pim;
        g_W[((size_t)h * Q + n) * T + l]      =  2.0f * wre;
        g_W[((size_t)h * Q + 32 + n) * T + l] = -2.0f * wim;
        float tre = pre * dre - pim * dimv; pim = pre * dimv + pim * dre; pre = tre;
        float ure = wre * dre - wim * dimv; wim = wre * dimv + wim * dre; wre = ure;
    }
}

// K0b: conv kernel K[h][l] = sum_n (2Cre*E - 2Cim*E_im), E row reversed
__global__ void k_K() {
    int i = blockIdx.x * blockDim.x + threadIdx.x;  // h*T + l
    if (i >= Hd * T) return;
    int h = i >> 6, l = i & 63;
    const float* e   = &g_E[((size_t)h * T + (T - 1 - l)) * Q];
    const float* c2r = &g_C2re[h * 32];
    const float* c2i = &g_C2imN[h * 32];
    float s = 0.0f;
    #pragma unroll 8
    for (int n = 0; n < 32; ++n)
        s = fmaf(c2r[n], e[n], fmaf(c2i[n], e[32 + n], s));
    g_K[i] = s;
}

// ---------------------------------------------------------------------------
// K-tr: transpose x [bt][h] -> xT [h][bt], 32x32 tiles
// ---------------------------------------------------------------------------
__global__ void __launch_bounds__(256) k_tr(const float* __restrict__ x) {
    __shared__ float tile[32 * 33];
    const int bt0 = blockIdx.x * 32;
    const int h0  = blockIdx.y * 32;
    const int tid = threadIdx.x;
    for (int k = tid; k < 1024; k += 256) {
        int r = k >> 5, hh = k & 31;
        tile[r * 33 + hh] = x[(size_t)(bt0 + r) * Hd + h0 + hh];
    }
    __syncthreads();
    for (int k = tid; k < 1024; k += 256) {
        int hh = k >> 5, r = k & 31;
        g_xT[(size_t)(h0 + hh) * BL + bt0 + r] = tile[r * 33 + hh];
    }
}

// ---------------------------------------------------------------------------
// K1: loc[h][q][cb] = sum_tau E[h][tau][q] * x[cb][tau]   (f32x2-packed GEMM)
// grid (Hd, CB/256), block 256
// ---------------------------------------------------------------------------
__global__ void __launch_bounds__(256) k_loc() {
    __shared__ __align__(16) float Es[T * Q];    // [tau][q] 16KB
    __shared__ float xrs[T * 33];                // [tau][c2]
    const int h = blockIdx.x;
    const int tid = threadIdx.x;
    for (int k = tid; k < T * Q; k += 256) Es[k] = g_E[(size_t)h * T * Q + k];
    const int cc = tid & 31, w = tid >> 5, q0 = w * 8;
    for (int ct = 0; ct < 8; ++ct) {
        const int cb0 = blockIdx.y * 256 + ct * 32;
        __syncthreads();
        for (int k = tid; k < 32 * T; k += 256) {
            int c2 = k >> 6, tau = k & 63;
            int cb = cb0 + c2, b = cb & 7, c = cb >> 3;
            xrs[tau * 33 + c2] = g_xT[(size_t)h * BL + b * L + c * T + tau];
        }
        __syncthreads();
        u64 a0 = 0, a1 = 0, a2 = 0, a3 = 0;
        #pragma unroll 8
        for (int tau = 0; tau < T; ++tau) {
            float xv = xrs[tau * 33 + cc];
            u64 x2 = pk2(xv, xv);
            const u64* ep = reinterpret_cast<const u64*>(&Es[tau * Q + q0]);
            a0 = fma2(ep[0], x2, a0);
            a1 = fma2(ep[1], x2, a1);
            a2 = fma2(ep[2], x2, a2);
            a3 = fma2(ep[3], x2, a3);
        }
        float2 f0 = upk2(a0), f1 = upk2(a1), f2 = upk2(a2), f3 = upk2(a3);
        size_t base = (size_t)h * Q * CB + cb0 + cc;
        g_loc[base + (size_t)(q0 + 0) * CB] = f0.x;
        g_loc[base + (size_t)(q0 + 1) * CB] = f0.y;
        g_loc[base + (size_t)(q0 + 2) * CB] = f1.x;
        g_loc[base + (size_t)(q0 + 3) * CB] = f1.y;
        g_loc[base + (size_t)(q0 + 4) * CB] = f2.x;
        g_loc[base + (size_t)(q0 + 5) * CB] = f2.y;
        g_loc[base + (size_t)(q0 + 6) * CB] = f3.x;
        g_loc[base + (size_t)(q0 + 7) * CB] = f3.y;
    }
}

// ---------------------------------------------------------------------------
// K2: carry scan over chunks (exclusive) + final state output.
// thread = (h, n, b); lanes cover 4n x 8b -> 32B-coalesced groups.
// ---------------------------------------------------------------------------
__global__ void k_carry(float* __restrict__ out, int stateMode) {
    int i = blockIdx.x * blockDim.x + threadIdx.x;
    if (i >= HN * B) return;
    int b = i & 7, n = (i >> 3) & 31, h = i >> 8;
    float aRe = g_dATre[h * 32 + n], aIm = g_dATim[h * 32 + n];
    const float* lre_p = &g_loc[((size_t)h * Q + n) * CB + b];
    const float* lim_p = &g_loc[((size_t)h * Q + 32 + n) * CB + b];
    float* sre_p = &g_S0[((size_t)h * Q + n) * CB + b];
    float* sim_p = &g_S0[((size_t)h * Q + 32 + n) * CB + b];
    float cre = 0.0f, cim = 0.0f;
    #pragma unroll 4
    for (int c = 0; c < NCH; ++c) {
        float lre = __ldg(lre_p + c * 8);
        float lim = __ldg(lim_p + c * 8);
        sre_p[c * 8] = cre;
        sim_p[c * 8] = cim;
        float nre = fmaf(aRe, cre, fmaf(-aIm, cim, lre));
        float nim = fmaf(aIm, cre, fmaf(aRe, cim, lim));
        cre = nre; cim = nim;
    }
    if (stateMode > 0) {
        size_t ysEnd = (size_t)B * L * Hd;
        size_t idx = ((size_t)b * Hd + h) * N2 + n;
        out[ysEnd + idx] = cre;
        if (stateMode > 1) out[ysEnd + (size_t)B * Hd * N2 + idx] = cim;
    }
}

// ---------------------------------------------------------------------------
// K3: corr[h][cb][t] = sum_q W[h][q][t] * S0[h][q][cb]  (f32x2-packed GEMM,
// smem-staged coalesced output). grid (Hd, CB/256), block 256
// ---------------------------------------------------------------------------
__global__ void __launch_bounds__(256) k_corr() {
    __shared__ __align__(16) float Ws[Q * T];    // [q][t] 16KB
    __shared__ float s0s[Q * 33];                // [q][c2]
    __shared__ __align__(16) float stg[32 * 68]; // [c2][t] staging
    const int h = blockIdx.x;
    const int tid = threadIdx.x;
    for (int k = tid; k < Q * T; k += 256) Ws[k] = g_W[(size_t)h * Q * T + k];
    const int cc = tid & 31, w = tid >> 5, t0 = w * 8;
    for (int ct = 0; ct < 8; ++ct) {
        const int cb0 = blockIdx.y * 256 + ct * 32;
        __syncthreads();
        for (int k = tid; k < 32 * Q; k += 256) {
            int q = k >> 5, c2 = k & 31;
            s0s[q * 33 + c2] = g_S0[((size_t)h * Q + q) * CB + cb0 + c2];
        }
        __syncthreads();
        u64 a0 = 0, a1 = 0, a2 = 0, a3 = 0;
        #pragma unroll 8
        for (int q = 0; q < Q; ++q) {
            float sv = s0s[q * 33 + cc];
            u64 s2 = pk2(sv, sv);
            const u64* wp = reinterpret_cast<const u64*>(&Ws[q * T + t0]);
            a0 = fma2(wp[0], s2, a0);
            a1 = fma2(wp[1], s2, a1);
            a2 = fma2(wp[2], s2, a2);
            a3 = fma2(wp[3], s2, a3);
        }
        float2 f0 = upk2(a0), f1 = upk2(a1), f2 = upk2(a2), f3 = upk2(a3);
        float4* sp = reinterpret_cast<float4*>(&stg[cc * 68 + t0]);
        sp[0] = make_float4(f0.x, f0.y, f1.x, f1.y);
        sp[1] = make_float4(f2.x, f2.y, f3.x, f3.y);
        __syncthreads();
        for (int k = tid; k < 1024; k += 256) {
            int r = k >> 5, p = k & 31;
            *reinterpret_cast<float2*>(&g_corr[((size_t)h * CB + cb0 + r) * T + 2 * p]) =
                *reinterpret_cast<const float2*>(&stg[r * 68 + 2 * p]);
        }
    }
}

// ---------------------------------------------------------------------------
// K4: output = causal conv(K,x) + corr + D*x, then exact GELU.
// grid (CB, Hd/32), block 256: 32 h-lanes x 8 t-octet warps
// ---------------------------------------------------------------------------
__global__ void __launch_bounds__(256) k_out(const float* __restrict__ x,
                                             const float* __restrict__ Dv,
                                             float* __restrict__ out) {
    __shared__ float xs[32 * 133];   // [hh][row], rows: 63 zero-pad + 64 real
    __shared__ float Ks[32 * 65];    // [hh][l]
    __shared__ float cs[32 * 65];    // [hh][t] staged corr
    const int cb = blockIdx.x, h0 = blockIdx.y * 32;
    const int b = cb & 7, c = cb >> 3;
    const int tid = threadIdx.x;
    for (int k = tid; k < 32 * 63; k += 256) {
        int hh = k & 31, r = k >> 5;
        xs[hh * 133 + r] = 0.0f;
    }
    for (int k = tid; k < 32 * 64; k += 256) {
        int hh = k & 31, tt = k >> 5;
        xs[hh * 133 + 63 + tt] = x[((size_t)b * L + c * T + tt) * Hd + h0 + hh];
    }
    for (int k = tid; k < 32 * 64; k += 256) {
        int hh = k & 31, l = k >> 5;
        Ks[hh * 65 + l] = g_K[(h0 + hh) * T + l];
    }
    for (int k = tid; k < 2048; k += 256) {
        int hh = k >> 6, tt = k & 63;
        cs[hh * 65 + tt] = g_corr[((size_t)(h0 + hh) * CB + cb) * T + tt];
    }
    __syncthreads();

    const int hh = tid & 31, w = tid >> 5, t0 = w * 8;
    float acc[8];
    #pragma unroll
    for (int j = 0; j < 8; ++j) acc[j] = cs[hh * 65 + t0 + j];

    const float* xrow = &xs[hh * 133];
    const float* krow = &Ks[hh * 65];
    for (int lt = 0; lt <= w; ++lt) {     // triangular skip (warp-uniform)
        const int l0 = lt * 8;
        const int rb = 63 + t0 - l0 - 7;
        float xw[15];
        #pragma unroll
        for (int j = 0; j < 15; ++j) xw[j] = xrow[rb + j];
        float kk[8];
        #pragma unroll
        for (int i = 0; i < 8; ++i) kk[i] = krow[l0 + i];
        #pragma unroll
        for (int i = 0; i < 8; ++i)
            #pragma unroll
            for (int j = 0; j < 8; ++j)
                acc[j] = fmaf(kk[i], xw[7 + j - i], acc[j]);
    }

    const float Dh = Dv[h0 + hh];
    #pragma unroll
    for (int j = 0; j < 8; ++j) {
        float xv = xrow[63 + t0 + j];
        float yv = fmaf(Dh, xv, acc[j]);
        float g = 0.5f * yv * (1.0f + erff(yv * 0.70710678118654752f));
        out[((size_t)b * L + c * T + t0 + j) * Hd + h0 + hh] = g;
    }
}

// ---------------------------------------------------------------------------
// Launch
// ---------------------------------------------------------------------------
extern "C" void kernel_launch(void* const* d_in, const int* in_sizes, int n_in,
                              void* d_out, int out_size) {
    const float* x      = (const float*)d_in[0];
    const float* log_dt = (const float*)d_in[1];
    const float* arl    = (const float*)d_in[2];
    const float* aim    = (const float*)d_in[3];
    const float* Bre    = (const float*)d_in[4];
    const float* Bim    = (const float*)d_in[5];
    const float* Cre    = (const float*)d_in[6];
    const float* Cim    = (const float*)d_in[7];
    const float* Dv     = (const float*)d_in[8];
    float* out = (float*)d_out;

    const long long ysElems = (long long)B * L * Hd;   // 16,777,216
    const long long stN     = (long long)B * Hd * N2;  // 131,072
    int stateMode = 0;
    if ((long long)out_size >= ysElems + 2 * stN) stateMode = 2;
    else if ((long long)out_size >= ysElems + stN) stateMode = 1;

    k_prep<<<(HN + 255) / 256, 256>>>(log_dt, arl, aim, Bre, Bim, Cre, Cim);
    k_K<<<(Hd * T + 255) / 256, 256>>>();
    k_tr<<<dim3(BL / 32, Hd / 32), 256>>>(x);
    k_loc<<<dim3(Hd, CB / 256), 256>>>();
    k_carry<<<(HN * B + 255) / 256, 256>>>(out, stateMode);
    k_corr<<<dim3(Hd, CB / 256), 256>>>();
    k_out<<<dim3(CB, Hd / 32), 256>>>(x, Dv, out);
}

// round 9
// speedup vs baseline: 1.3013x; 1.1765x over previous
#include <cuda_runtime.h>
#include <math.h>

// Problem constants
#define Hd 512
#define L 4096
#define B 8
#define N2 32
#define HN (Hd * N2)
#define T 64            // chunk length
#define NCH (L / T)     // 64 chunks per sequence
#define CB (NCH * B)    // 512 chunk-rows
#define Q 64            // 2*N2 (re block + im block)
#define BL (B * L)      // 32768
#define CBP 516         // padded locS row stride (floats)
#define XRP 132         // padded xrs row stride
#define STP 66          // stg row stride

typedef unsigned long long u64;

__device__ __forceinline__ u64 pk2(float lo, float hi) {
    u64 r; asm("mov.b64 %0, {%1, %2};" : "=l"(r) : "f"(lo), "f"(hi)); return r;
}
__device__ __forceinline__ float2 upk2(u64 v) {
    float2 f; asm("mov.b64 {%0, %1}, %2;" : "=f"(f.x), "=f"(f.y) : "l"(v)); return f;
}
__device__ __forceinline__ u64 fma2(u64 a, u64 b, u64 c) {
    u64 d; asm("fma.rn.f32x2 %0, %1, %2, %3;" : "=l"(d) : "l"(a), "l"(b), "l"(c)); return d;
}

// ---------------------------------------------------------------------------
// Device-global parameter / scratch arrays
// ---------------------------------------------------------------------------
__device__ float g_C2re[HN], g_C2imN[HN];
__device__ float g_dATre[HN], g_dATim[HN];                  // dA^T (double-derived)
__device__ __align__(16) float g_E[Hd * T * Q];             // [h][tau][q]: dA^{T-1-tau} dB
__device__ __align__(16) float g_Wt[Hd * T * Q];            // [h][t][q] (prep output)
__device__ __align__(16) float g_W[Hd * Q * T];             // [h][q][t] (transposed)
__device__ float g_K[Hd * T];                               // conv kernel
__device__ __align__(16) float g_xT[(size_t)Hd * BL];       // transposed x: [h][b*L+t]
__device__ __align__(16) float g_loc[(size_t)Hd * Q * CB];  // [h][q][cb]
__device__ __align__(16) float g_corr[(size_t)Hd * CB * T]; // [h][cb][t]

// ---------------------------------------------------------------------------
// K0: per-(h,n) discretization + E/Wt tables
// ---------------------------------------------------------------------------
__global__ void k_prep(const float* __restrict__ log_dt,
                       const float* __restrict__ arl,
                       const float* __restrict__ aim,
                       const float* __restrict__ Bre,
                       const float* __restrict__ Bim,
                       const float* __restrict__ Cre,
                       const float* __restrict__ Cim) {
    int i = blockIdx.x * blockDim.x + threadIdx.x;
    if (i >= HN) return;
    int h = i >> 5, n = i & 31;
    float dt   = expf(log_dt[h]);
    float are  = -expf(arl[i]);
    float aimv = aim[i];
    float zre = are * dt, zim = aimv * dt;
    float sz, cz; sincosf(zim, &sz, &cz);
    float ez = expf(zre);
    float dre = ez * cz, dimv = ez * sz;   // dA
    float sh = sinf(0.5f * zim);
    float em1re = expm1f(zre) * cz - 2.0f * sh * sh;
    float em1im = ez * sz;
    float inv = 1.0f / (are * are + aimv * aimv);
    float fre = (em1re * are + em1im * aimv) * inv;
    float fim = (em1im * are - em1re * aimv) * inv;
    float bre0 = Bre[i], bim0 = Bim[i];
    float dbre = bre0 * fre - bim0 * fim;
    float dbim = bre0 * fim + bim0 * fre;
    g_C2re[i]  =  2.0f * Cre[i];
    g_C2imN[i] = -2.0f * Cim[i];
    double zred = (double)are * (double)dt * (double)T;
    double zimd = (double)aimv * (double)dt * (double)T;
    double ezd = exp(zred);
    g_dATre[i] = (float)(ezd * cos(zimd));
    g_dATim[i] = (float)(ezd * sin(zimd));
    // E[tau] = dA^{T-1-tau} dB (reversed rows) ; Wt[t][q] = C dA^{t+1}
    float pre = dbre, pim = dbim;
    float cre0 = Cre[i], cim0 = Cim[i];
    float wre = cre0 * dre - cim0 * dimv;
    float wim = cre0 * dimv + cim0 * dre;
    for (int l = 0; l < T; ++l) {
        g_E[((size_t)h * T + (T - 1 - l)) * Q + n]      = pre;
        g_E[((size_t)h * T + (T - 1 - l)) * Q + 32 + n] = pim;
        g_Wt[((size_t)h * T + l) * Q + n]      =  2.0f * wre;
        g_Wt[((size_t)h * T + l) * Q + 32 + n] = -2.0f * wim;
        float tre = pre * dre - pim * dimv; pim = pre * dimv + pim * dre; pre = tre;
        float ure = wre * dre - wim * dimv; wim = wre * dimv + wim * dre; wre = ure;
    }
}

// K0b: conv kernel K[h][l]
__global__ void k_K() {
    int i = blockIdx.x * blockDim.x + threadIdx.x;
    if (i >= Hd * T) return;
    int h = i >> 6, l = i & 63;
    const float* e   = &g_E[((size_t)h * T + (T - 1 - l)) * Q];
    const float* c2r = &g_C2re[h * 32];
    const float* c2i = &g_C2imN[h * 32];
    float s = 0.0f;
    #pragma unroll 8
    for (int n = 0; n < 32; ++n)
        s = fmaf(c2r[n], e[n], fmaf(c2i[n], e[32 + n], s));
    g_K[i] = s;
}

// K0c: per-h transpose Wt[t][q] -> W[q][t]
__global__ void __launch_bounds__(256) k_wtr() {
    __shared__ float wt[T * 68];
    const int h = blockIdx.x, tid = threadIdx.x;
    for (int k = tid; k < T * Q / 4; k += 256) {
        int t = k >> 4, qq = (k & 15) * 4;
        *reinterpret_cast<float4*>(&wt[t * 68 + qq]) =
            reinterpret_cast<const float4*>(g_Wt + (size_t)h * T * Q)[k];
    }
    __syncthreads();
    for (int k = tid; k < Q * T / 4; k += 256) {
        int q = k >> 4, tq = (k & 15) * 4;
        float4 v = make_float4(wt[(tq + 0) * 68 + q], wt[(tq + 1) * 68 + q],
                               wt[(tq + 2) * 68 + q], wt[(tq + 3) * 68 + q]);
        *reinterpret_cast<float4*>(&g_W[((size_t)h * Q + q) * T + tq]) = v;
    }
}

// ---------------------------------------------------------------------------
// K-tr: transpose x [bt][h] -> xT [h][bt]
// ---------------------------------------------------------------------------
__global__ void __launch_bounds__(256) k_tr(const float* __restrict__ x) {
    __shared__ float tile[32 * 33];
    const int bt0 = blockIdx.x * 32;
    const int h0  = blockIdx.y * 32;
    const int tid = threadIdx.x;
    for (int k = tid; k < 1024; k += 256) {
        int r = k >> 5, hh = k & 31;
        tile[r * 33 + hh] = x[(size_t)(bt0 + r) * Hd + h0 + hh];
    }
    __syncthreads();
    for (int k = tid; k < 1024; k += 256) {
        int hh = k >> 5, r = k & 31;
        g_xT[(size_t)(h0 + hh) * BL + bt0 + r] = tile[r * 33 + hh];
    }
}

// ---------------------------------------------------------------------------
// K1: loc[h][q][cb] = sum_tau E[h][tau][q] * x[cb][tau]
// 4 cb per lane, f32x2. grid (Hd, CB/128), block 256, dynamic smem.
// ---------------------------------------------------------------------------
__global__ void __launch_bounds__(256) k_loc() {
    extern __shared__ float sm[];
    float* Es  = sm;                // [64][64] 16KB
    float* xrs = sm + T * Q;        // [64][XRP] 33.8KB
    const int h = blockIdx.x;
    const int cb0 = blockIdx.y * 128;
    const int tid = threadIdx.x;
    for (int k = tid; k < T * Q / 4; k += 256)
        reinterpret_cast<float4*>(Es)[k] =
            reinterpret_cast<const float4*>(g_E + (size_t)h * T * Q)[k];
    for (int k = tid; k < 128 * T; k += 256) {
        int c2 = k >> 6, tau = k & 63;
        int cb = cb0 + c2, b = cb & 7, c = cb >> 3;
        xrs[tau * XRP + c2] = g_xT[(size_t)h * BL + b * L + c * T + tau];
    }
    __syncthreads();
    const int cc = tid & 31, w = tid >> 5, q0 = w * 8;
    u64 acc[4][4];
    #pragma unroll
    for (int a = 0; a < 4; ++a)
        #pragma unroll
        for (int p = 0; p < 4; ++p) acc[a][p] = 0ull;
    #pragma unroll 4
    for (int tau = 0; tau < T; ++tau) {
        float4 xv = *reinterpret_cast<const float4*>(&xrs[tau * XRP + cc * 4]);
        ulonglong2 ea = *reinterpret_cast<const ulonglong2*>(&Es[tau * Q + q0]);
        ulonglong2 eb = *reinterpret_cast<const ulonglong2*>(&Es[tau * Q + q0 + 4]);
        u64 xx;
        xx = pk2(xv.x, xv.x);
        acc[0][0] = fma2(ea.x, xx, acc[0][0]); acc[0][1] = fma2(ea.y, xx, acc[0][1]);
        acc[0][2] = fma2(eb.x, xx, acc[0][2]); acc[0][3] = fma2(eb.y, xx, acc[0][3]);
        xx = pk2(xv.y, xv.y);
        acc[1][0] = fma2(ea.x, xx, acc[1][0]); acc[1][1] = fma2(ea.y, xx, acc[1][1]);
        acc[1][2] = fma2(eb.x, xx, acc[1][2]); acc[1][3] = fma2(eb.y, xx, acc[1][3]);
        xx = pk2(xv.z, xv.z);
        acc[2][0] = fma2(ea.x, xx, acc[2][0]); acc[2][1] = fma2(ea.y, xx, acc[2][1]);
        acc[2][2] = fma2(eb.x, xx, acc[2][2]); acc[2][3] = fma2(eb.y, xx, acc[2][3]);
        xx = pk2(xv.w, xv.w);
        acc[3][0] = fma2(ea.x, xx, acc[3][0]); acc[3][1] = fma2(ea.y, xx, acc[3][1]);
        acc[3][2] = fma2(eb.x, xx, acc[3][2]); acc[3][3] = fma2(eb.y, xx, acc[3][3]);
    }
    #pragma unroll
    for (int p = 0; p < 4; ++p) {
        float2 f0 = upk2(acc[0][p]), f1 = upk2(acc[1][p]);
        float2 f2 = upk2(acc[2][p]), f3 = upk2(acc[3][p]);
        int q = q0 + 2 * p;
        *reinterpret_cast<float4*>(&g_loc[((size_t)h * Q + q) * CB + cb0 + cc * 4]) =
            make_float4(f0.x, f1.x, f2.x, f3.x);
        *reinterpret_cast<float4*>(&g_loc[((size_t)h * Q + q + 1) * CB + cb0 + cc * 4]) =
            make_float4(f0.y, f1.y, f2.y, f3.y);
    }
}

// ---------------------------------------------------------------------------
// K2: fused carry-scan + correction GEMM. One block per h.
// smem: locS [Q][CBP] + Ws [Q][T] + stg [128][STP]
// ---------------------------------------------------------------------------
__global__ void __launch_bounds__(256) k_corrf(float* __restrict__ out, int stateMode) {
    extern __shared__ float sm[];
    float* locS = sm;                    // 64*516 = 132KB
    float* Ws   = sm + Q * CBP;          // 16KB
    float* stg  = Ws + Q * T;            // 128*66 = 33.8KB
    const int h = blockIdx.x;
    const int tid = threadIdx.x;
    for (int k = tid; k < Q * T / 4; k += 256)
        reinterpret_cast<float4*>(Ws)[k] =
            reinterpret_cast<const float4*>(g_W + (size_t)h * Q * T)[k];
    for (int k = tid; k < Q * CB / 4; k += 256) {
        int q = k >> 7, c4 = k & 127;
        *reinterpret_cast<float4*>(&locS[q * CBP + c4 * 4]) =
            reinterpret_cast<const float4*>(g_loc + (size_t)h * Q * CB)[k];
    }
    __syncthreads();
    // exclusive carry scan along chunks, in place; thread = (n, b)
    {
        int n = tid >> 3, b = tid & 7;
        float aRe = g_dATre[h * 32 + n], aIm = g_dATim[h * 32 + n];
        float* pr = &locS[n * CBP + b];
        float* pi = &locS[(32 + n) * CBP + b];
        float cre = 0.0f, cim = 0.0f;
        #pragma unroll 4
        for (int c = 0; c < NCH; ++c) {
            float lre = pr[c * 8], lim = pi[c * 8];
            pr[c * 8] = cre; pi[c * 8] = cim;
            float nre = fmaf(aRe, cre, fmaf(-aIm, cim, lre));
            float nim = fmaf(aIm, cre, fmaf(aRe, cim, lim));
            cre = nre; cim = nim;
        }
        if (stateMode > 0) {
            size_t ysEnd = (size_t)B * L * Hd;
            size_t idx = ((size_t)b * Hd + h) * N2 + n;
            out[ysEnd + idx] = cre;
            if (stateMode > 1) out[ysEnd + (size_t)B * Hd * N2 + idx] = cim;
        }
    }
    __syncthreads();
    // correction GEMM: corr[cb][t] = sum_q W[q][t] * s0[q][cb]
    const int cc = tid & 31, w = tid >> 5, t0 = w * 8;
    for (int pass = 0; pass < 4; ++pass) {
        const int cbl0 = pass * 128;
        u64 acc[4][4];
        #pragma unroll
        for (int a = 0; a < 4; ++a)
            #pragma unroll
            for (int p = 0; p < 4; ++p) acc[a][p] = 0ull;
        #pragma unroll 4
        for (int q = 0; q < Q; ++q) {
            float4 sv = *reinterpret_cast<const float4*>(&locS[q * CBP + cbl0 + cc * 4]);
            ulonglong2 wa = *reinterpret_cast<const ulonglong2*>(&Ws[q * T + t0]);
            ulonglong2 wb = *reinterpret_cast<const ulonglong2*>(&Ws[q * T + t0 + 4]);
            u64 xx;
            xx = pk2(sv.x, sv.x);
            acc[0][0] = fma2(wa.x, xx, acc[0][0]); acc[0][1] = fma2(wa.y, xx, acc[0][1]);
            acc[0][2] = fma2(wb.x, xx, acc[0][2]); acc[0][3] = fma2(wb.y, xx, acc[0][3]);
            xx = pk2(sv.y, sv.y);
            acc[1][0] = fma2(wa.x, xx, acc[1][0]); acc[1][1] = fma2(wa.y, xx, acc[1][1]);
            acc[1][2] = fma2(wb.x, xx, acc[1][2]); acc[1][3] = fma2(wb.y, xx, acc[1][3]);
            xx = pk2(sv.z, sv.z);
            acc[2][0] = fma2(wa.x, xx, acc[2][0]); acc[2][1] = fma2(wa.y, xx, acc[2][1]);
            acc[2][2] = fma2(wb.x, xx, acc[2][2]); acc[2][3] = fma2(wb.y, xx, acc[2][3]);
            xx = pk2(sv.w, sv.w);
            acc[3][0] = fma2(wa.x, xx, acc[3][0]); acc[3][1] = fma2(wa.y, xx, acc[3][1]);
            acc[3][2] = fma2(wb.x, xx, acc[3][2]); acc[3][3] = fma2(wb.y, xx, acc[3][3]);
        }
        #pragma unroll
        for (int a = 0; a < 4; ++a) {
            float* row = &stg[(cc * 4 + a) * STP + t0];
            #pragma unroll
            for (int p = 0; p < 4; ++p) {
                float2 f = upk2(acc[a][p]);
                *reinterpret_cast<float2*>(&row[2 * p]) = f;
            }
        }
        __syncthreads();
        for (int k = tid; k < 128 * T / 4; k += 256) {
            int r = k >> 4, tp = (k & 15) * 4;
            float2 a = *reinterpret_cast<const float2*>(&stg[r * STP + tp]);
            float2 b2 = *reinterpret_cast<const float2*>(&stg[r * STP + tp + 2]);
            *reinterpret_cast<float4*>(&g_corr[((size_t)h * CB + cbl0 + r) * T + tp]) =
                make_float4(a.x, a.y, b2.x, b2.y);
        }
        __syncthreads();
    }
}

// ---------------------------------------------------------------------------
// K4: output = causal conv(K,x) + corr + D*x, then exact GELU.
// grid (CB, Hd/32), block 256
// ---------------------------------------------------------------------------
__global__ void __launch_bounds__(256) k_out(const float* __restrict__ x,
                                             const float* __restrict__ Dv,
                                             float* __restrict__ out) {
    __shared__ float xs[32 * 133];
    __shared__ float Ks[32 * 65];
    __shared__ float cs[32 * 65];
    const int cb = blockIdx.x, h0 = blockIdx.y * 32;
    const int b = cb & 7, c = cb >> 3;
    const int tid = threadIdx.x;
    for (int k = tid; k < 32 * 63; k += 256) {
        int hh = k & 31, r = k >> 5;
        xs[hh * 133 + r] = 0.0f;
    }
    for (int k = tid; k < 32 * 64; k += 256) {
        int hh = k & 31, tt = k >> 5;
        xs[hh * 133 + 63 + tt] = x[((size_t)b * L + c * T + tt) * Hd + h0 + hh];
    }
    for (int k = tid; k < 32 * 64; k += 256) {
        int hh = k & 31, l = k >> 5;
        Ks[hh * 65 + l] = g_K[(h0 + hh) * T + l];
    }
    for (int k = tid; k < 2048; k += 256) {
        int hh = k >> 6, tt = k & 63;
        cs[hh * 65 + tt] = g_corr[((size_t)(h0 + hh) * CB + cb) * T + tt];
    }
    __syncthreads();

    const int hh = tid & 31, w = tid >> 5, t0 = w * 8;
    float acc[8];
    #pragma unroll
    for (int j = 0; j < 8; ++j) acc[j] = cs[hh * 65 + t0 + j];

    const float* xrow = &xs[hh * 133];
    const float* krow = &Ks[hh * 65];
    for (int lt = 0; lt <= w; ++lt) {
        const int l0 = lt * 8;
        const int rb = 63 + t0 - l0 - 7;
        float xw[15];
        #pragma unroll
        for (int j = 0; j < 15; ++j) xw[j] = xrow[rb + j];
        float kk[8];
        #pragma unroll
        for (int i = 0; i < 8; ++i) kk[i] = krow[l0 + i];
        #pragma unroll
        for (int i = 0; i < 8; ++i)
            #pragma unroll
            for (int j = 0; j < 8; ++j)
                acc[j] = fmaf(kk[i], xw[7 + j - i], acc[j]);
    }

    const float Dh = Dv[h0 + hh];
    #pragma unroll
    for (int j = 0; j < 8; ++j) {
        float xv = xrow[63 + t0 + j];
        float yv = fmaf(Dh, xv, acc[j]);
        float g = 0.5f * yv * (1.0f + erff(yv * 0.70710678118654752f));
        out[((size_t)b * L + c * T + t0 + j) * Hd + h0 + hh] = g;
    }
}

// ---------------------------------------------------------------------------
// Launch
// ---------------------------------------------------------------------------
extern "C" void kernel_launch(void* const* d_in, const int* in_sizes, int n_in,
                              void* d_out, int out_size) {
    const float* x      = (const float*)d_in[0];
    const float* log_dt = (const float*)d_in[1];
    const float* arl    = (const float*)d_in[2];
    const float* aim    = (const float*)d_in[3];
    const float* Bre    = (const float*)d_in[4];
    const float* Bim    = (const float*)d_in[5];
    const float* Cre    = (const float*)d_in[6];
    const float* Cim    = (const float*)d_in[7];
    const float* Dv     = (const float*)d_in[8];
    float* out = (float*)d_out;

    const long long ysElems = (long long)B * L * Hd;   // 16,777,216
    const long long stN     = (long long)B * Hd * N2;  // 131,072
    int stateMode = 0;
    if ((long long)out_size >= ysElems + 2 * stN) stateMode = 2;
    else if ((long long)out_size >= ysElems + stN) stateMode = 1;

    const int locSmem  = (T * Q + T * XRP) * 4;                 // 50,176 B
    const int corrSmem = (Q * CBP + Q * T + 128 * STP) * 4;     // 182,272 B
    static int attrDone = 0;
    if (!attrDone) {
        cudaFuncSetAttribute(k_loc, cudaFuncAttributeMaxDynamicSharedMemorySize, locSmem);
        cudaFuncSetAttribute(k_corrf, cudaFuncAttributeMaxDynamicSharedMemorySize, corrSmem);
        attrDone = 1;
    }

    k_prep<<<(HN + 255) / 256, 256>>>(log_dt, arl, aim, Bre, Bim, Cre, Cim);
    k_K<<<(Hd * T + 255) / 256, 256>>>();
    k_wtr<<<Hd, 256>>>();
    k_tr<<<dim3(BL / 32, Hd / 32), 256>>>(x);
    k_loc<<<dim3(Hd, CB / 128), 256, locSmem>>>();
    k_corrf<<<Hd, 256, corrSmem>>>(out, stateMode);
    k_out<<<dim3(CB, Hd / 32), 256>>>(x, Dv, out);
}